// round 11
// baseline (speedup 1.0000x reference)
#include <cuda_runtime.h>
#include <cstdint>

// WindowAttention fused kernel, round 7.
// fp32 f32x2-packed FFMA, one CTA per window, 256 threads.
// - 2-head QKV passes (C=6 per lane), double-buffered cp.async weight staging.
// - tbl/mask/rpi read from gmem (L2-hot), K tiles restrided for LDS.128.
//
// Inputs (metadata order):
//  0 x(8192,49,384) f32   1 mask(64,49,49) f32   2 rel_pos_table(169,12) f32
//  3 qkv_w(1152,384) f32  4 qkv_b(1152) f32      5 proj_w(384,384) f32
//  6 proj_b(384) f32      7 rel_pos_index(49,49) i32
// out (8192,49,384) f32

#define NTOK   49
#define NH     12
#define HDM    32
#define DIMM   384
#define NWIN   64
#define SCALE  0.17677669529663687f   // 1/sqrt(32)

// shared memory layout (float offsets)
#define OFF_XS 0            // 49*384 = 18816 (A reads are warp-broadcast: no pad)
#define OFF_OS 18816        // 49*384 = 18816
#define OFF_WS 37632        // 2 * 192*20 = 7680  (double-buffered W tiles, K-chunk 16)
#define OFF_QS 45312        // 2 * 49*32 = 3136
#define OFF_KS 48448        // 2 * 49*36 = 3528   (stride 36: LDS.128 conflict-free)
#define OFF_VS 51976        // 2 * 49*32 = 3136
#define OFF_PS 55112        // 49*52 = 2548       (stride 52: float4-aligned)
#define SMEM_FLOATS 57660   // 230,640 bytes (< 232,448 cap)

#define WBUF_F 3840         // floats per W buffer (192*20)
#define WBUF_B 15360        // bytes per W buffer

typedef unsigned long long u64;

// packed dual-fp32 FMA (sm_100+ FFMA2 pipe)
__device__ __forceinline__ void fma2(u64& d, u64 a, u64 b) {
    asm("fma.rn.f32x2 %0, %1, %2, %3;" : "=l"(d) : "l"(a), "l"(b), "l"(d));
}
__device__ __forceinline__ float unpack_add(u64 v) {
    float lo, hi;
    asm("mov.b64 {%0, %1}, %2;" : "=f"(lo), "=f"(hi) : "l"(v));
    return lo + hi;
}
__device__ __forceinline__ void cp16(uint32_t s, const float* g) {
    asm volatile("cp.async.cg.shared.global [%0], [%1], 16;" :: "r"(s), "l"(g));
}
__device__ __forceinline__ void cp_commit() {
    asm volatile("cp.async.commit_group;" ::: "memory");
}
__device__ __forceinline__ void cp_wait0() {
    asm volatile("cp.async.wait_group 0;" ::: "memory");
}

// C[49][192] = A[49][384](smem) @ W[192 rows][384]^T, W rows selected by QKV/base.
// Warp w owns rows {w+8j, j=0..6} (j==6 only warp 0). Lane owns cols lane+32*cc.
// W tiles double-buffered through smem via cp.async (K-chunk = 16).
template<bool QKV>
__device__ __forceinline__ void gemm192(const float* __restrict__ A,
                                        const float* __restrict__ Wg,
                                        int base,            // h0*HDM (QKV) or col base (proj)
                                        float* __restrict__ WS, uint32_t ws_u32,
                                        float fin[7][6],
                                        int tid, int lane, int warp)
{
    u64 acc[7][6];
#pragma unroll
    for (int j = 0; j < 7; j++)
#pragma unroll
        for (int c = 0; c < 6; c++) acc[j][c] = 0ull;

    // per-thread staging addresses (chunk-invariant)
    const float* gsrc[3];
    uint32_t     sdst[3];
#pragma unroll
    for (int t = 0; t < 3; t++) {
        int i  = tid + 256 * t;          // 0..767 : 192 rows x 4 float4
        int rw = i >> 2, q4 = i & 3;
        int orow = QKV ? ((rw >> 6) * DIMM + base + ((rw >> 5) & 1) * HDM + (rw & 31))
                       : (base + rw);
        gsrc[t] = Wg + (size_t)orow * DIMM + q4 * 4;
        sdst[t] = ws_u32 + (uint32_t)((rw * 20 + q4 * 4) * 4);
    }

    // prologue: stage chunk 0 -> buf 0
#pragma unroll
    for (int t = 0; t < 3; t++) cp16(sdst[t], gsrc[t]);
    cp_commit();

    const float* Ab = A + warp * DIMM;

#pragma unroll 1
    for (int c = 0; c < 24; c++) {
        cp_wait0();
        __syncthreads();                 // chunk c visible to all; prior reads done
        if (c + 1 < 24) {                // prefetch chunk c+1 into other buffer
            int kk2 = (c + 1) * 16;
            uint32_t bo = ((c + 1) & 1) * WBUF_B;
#pragma unroll
            for (int t = 0; t < 3; t++) cp16(sdst[t] + bo, gsrc[t] + kk2);
            cp_commit();
        }
        const float* Wb = WS + (c & 1) * WBUF_F;
        const float* Ac = Ab + c * 16;
#pragma unroll
        for (int k4 = 0; k4 < 4; k4++) {
            ulonglong2 b[6];
#pragma unroll
            for (int cc = 0; cc < 6; cc++)
                b[cc] = *(const ulonglong2*)&Wb[(lane + 32 * cc) * 20 + k4 * 4];
#pragma unroll
            for (int j = 0; j < 7; j++) {
                if (j < 6 || warp == 0) {
                    ulonglong2 a = *(const ulonglong2*)&Ac[j * 8 * DIMM + k4 * 4];
#pragma unroll
                    for (int cc = 0; cc < 6; cc++) {
                        fma2(acc[j][cc], a.x, b[cc].x);
                        fma2(acc[j][cc], a.y, b[cc].y);
                    }
                }
            }
        }
    }
#pragma unroll
    for (int j = 0; j < 7; j++)
#pragma unroll
        for (int c = 0; c < 6; c++) fin[j][c] = unpack_add(acc[j][c]);
}

__global__ __launch_bounds__(256, 1)
void win_attn_kernel(const float* __restrict__ x,
                     const float* __restrict__ mask,
                     const float* __restrict__ tbl,
                     const float* __restrict__ qkv_w,
                     const float* __restrict__ qkv_b,
                     const float* __restrict__ proj_w,
                     const float* __restrict__ proj_b,
                     const int*   __restrict__ rpi,
                     float* __restrict__ out)
{
    extern __shared__ float sm[];
    float* XS = sm + OFF_XS;
    float* OS = sm + OFF_OS;
    float* WS = sm + OFF_WS;
    float* QS = sm + OFF_QS;
    float* KS = sm + OFF_KS;
    float* VS = sm + OFF_VS;
    float* PS = sm + OFF_PS;
    const uint32_t ws_u32 = (uint32_t)__cvta_generic_to_shared(WS);

    const int tid  = threadIdx.x;
    const int lane = tid & 31;
    const int warp = tid >> 5;
    const int b    = blockIdx.x;
    const int wm   = b & (NWIN - 1);
    const float* mw = mask + (size_t)wm * NTOK * NTOK;

    // load x tile (49x384), vectorized; ordered by first gemm barrier
    const float4* x4 = (const float4*)(x + (size_t)b * NTOK * DIMM);
    float4* xs4 = (float4*)XS;
    for (int i = tid; i < NTOK * (DIMM / 4); i += 256) xs4[i] = x4[i];

    const bool v2  = (lane + 32) < NTOK;
    const int  jc2 = v2 ? lane + 32 : 0;

#pragma unroll 1
    for (int p = 0; p < NH / 2; p++) {          // 6 passes, 2 heads each
        const int h0 = 2 * p;
        float fin[7][6];
        gemm192<true>(XS, qkv_w, h0 * HDM, WS, ws_u32, fin, tid, lane, warp);

        // store q (pre-scaled), k, v for both heads
#pragma unroll
        for (int h2 = 0; h2 < 2; h2++) {
            float bq = qkv_b[      h0 * HDM + h2 * HDM + lane];
            float bk = qkv_b[384 + h0 * HDM + h2 * HDM + lane];
            float bv = qkv_b[768 + h0 * HDM + h2 * HDM + lane];
#pragma unroll
            for (int j = 0; j < 7; j++) {
                if (j < 6 || warp == 0) {
                    int r = warp + 8 * j;
                    QS[h2 * 1568 + r * 32 + lane] = (fin[j][h2]     + bq) * SCALE;
                    KS[h2 * 1764 + r * 36 + lane] =  fin[j][2 + h2] + bk;
                    VS[h2 * 1568 + r * 32 + lane] =  fin[j][4 + h2] + bv;
                }
            }
        }
        __syncthreads();

#pragma unroll 1
        for (int h2 = 0; h2 < 2; h2++) {
            const int h = h0 + h2;
            const float* Qh = QS + h2 * 1568;
            const float* Kh = KS + h2 * 1764;
            const float* Vh = VS + h2 * 1568;

            // ---- scores + bias + mask + softmax (warp per row set) ----
#pragma unroll
            for (int j = 0; j < 7; j++) {
                if (j == 6 && warp != 0) break;
                int r = warp + 8 * j;
                // bias/mask lookups (L2/L1-hot), issued before the dot loop
                int   i1 = rpi[r * NTOK + lane];
                float m1 = mw [r * NTOK + lane];
                int   i2 = v2 ? rpi[r * NTOK + lane + 32] : 0;
                float m2 = v2 ? mw [r * NTOK + lane + 32] : 0.f;
                float t1 = tbl[i1 * NH + h];
                float t2 = tbl[i2 * NH + h];
                float s1 = 0.f, s2 = 0.f;
#pragma unroll
                for (int dq = 0; dq < 8; dq++) {
                    float4 q  = *(const float4*)&Qh[r   * 32 + dq * 4];
                    float4 k1 = *(const float4*)&Kh[lane * 36 + dq * 4];
                    float4 k2 = *(const float4*)&Kh[jc2  * 36 + dq * 4];
                    s1 = fmaf(q.x, k1.x, s1); s1 = fmaf(q.y, k1.y, s1);
                    s1 = fmaf(q.z, k1.z, s1); s1 = fmaf(q.w, k1.w, s1);
                    s2 = fmaf(q.x, k2.x, s2); s2 = fmaf(q.y, k2.y, s2);
                    s2 = fmaf(q.z, k2.z, s2); s2 = fmaf(q.w, k2.w, s2);
                }
                s1 += t1 + m1;
                s2 = v2 ? (s2 + t2 + m2) : -1e30f;
                float mx = fmaxf(s1, s2);
#pragma unroll
                for (int o = 16; o > 0; o >>= 1)
                    mx = fmaxf(mx, __shfl_xor_sync(0xffffffffu, mx, o));
                float e1 = __expf(s1 - mx);
                float e2 = v2 ? __expf(s2 - mx) : 0.f;
                float sum = e1 + e2;
#pragma unroll
                for (int o = 16; o > 0; o >>= 1)
                    sum += __shfl_xor_sync(0xffffffffu, sum, o);
                float inv = 1.0f / sum;
                PS[r * 52 + lane] = e1 * inv;
                if (v2) PS[r * 52 + lane + 32] = e2 * inv;
            }
            __syncwarp();

            // ---- P @ V (V loads shared across the 7 rows) ----
            float o[7];
#pragma unroll
            for (int j = 0; j < 7; j++) o[j] = 0.f;
#pragma unroll 3
            for (int jq = 0; jq < 12; jq++) {
                float va = Vh[(4 * jq + 0) * 32 + lane];
                float vb = Vh[(4 * jq + 1) * 32 + lane];
                float vc = Vh[(4 * jq + 2) * 32 + lane];
                float vd = Vh[(4 * jq + 3) * 32 + lane];
#pragma unroll
                for (int j = 0; j < 7; j++) {
                    if (j < 6 || warp == 0) {
                        float4 pp = *(const float4*)&PS[(warp + 8 * j) * 52 + 4 * jq];
                        o[j] = fmaf(pp.x, va, o[j]);
                        o[j] = fmaf(pp.y, vb, o[j]);
                        o[j] = fmaf(pp.z, vc, o[j]);
                        o[j] = fmaf(pp.w, vd, o[j]);
                    }
                }
            }
            float vt = Vh[48 * 32 + lane];
#pragma unroll
            for (int j = 0; j < 7; j++) {
                if (j < 6 || warp == 0) {
                    int r = warp + 8 * j;
                    o[j] = fmaf(PS[r * 52 + 48], vt, o[j]);
                    OS[r * DIMM + h * HDM + lane] = o[j];
                }
            }
            __syncwarp();   // PS reads done before next head overwrites
        }
        // next pass's gemm barriers order VS/QS/KS reuse
    }

    // ---- projection: out = OS @ proj_w^T + proj_b, two 192-col passes ----
    float* outb = out + (size_t)b * NTOK * DIMM;
#pragma unroll 1
    for (int c0 = 0; c0 < DIMM; c0 += 192) {
        float fin[7][6];
        gemm192<false>(OS, proj_w, c0, WS, ws_u32, fin, tid, lane, warp);
        float pb[6];
#pragma unroll
        for (int cc = 0; cc < 6; cc++) pb[cc] = proj_b[c0 + lane + 32 * cc];
#pragma unroll
        for (int j = 0; j < 7; j++) {
            if (j < 6 || warp == 0) {
                int r = warp + 8 * j;
#pragma unroll
                for (int cc = 0; cc < 6; cc++)
                    outb[r * DIMM + c0 + lane + 32 * cc] = fin[j][cc] + pb[cc];
            }
        }
    }
}

extern "C" void kernel_launch(void* const* d_in, const int* in_sizes, int n_in,
                              void* d_out, int out_size)
{
    const float* x      = (const float*)d_in[0];
    const float* mask   = (const float*)d_in[1];
    const float* tbl    = (const float*)d_in[2];
    const float* qkv_w  = (const float*)d_in[3];
    const float* qkv_b  = (const float*)d_in[4];
    const float* proj_w = (const float*)d_in[5];
    const float* proj_b = (const float*)d_in[6];
    const int*   rpi    = (const int*)d_in[7];
    float* out = (float*)d_out;

    int B = in_sizes[0] / (NTOK * DIMM);   // 8192
    size_t smem = (size_t)SMEM_FLOATS * sizeof(float);   // 230,640 B
    cudaFuncSetAttribute(win_attn_kernel,
                         cudaFuncAttributeMaxDynamicSharedMemorySize, (int)smem);
    win_attn_kernel<<<B, 256, smem>>>(x, mask, tbl, qkv_w, qkv_b,
                                      proj_w, proj_b, rpi, out);
}

// round 17
// speedup vs baseline: 2.4563x; 2.4563x over previous
#include <cuda_runtime.h>
#include <cuda_bf16.h>
#include <cstdint>

// WindowAttention: split-bf16 mma.sync (HMMA) GEMMs + fp32 attention.
// (tcgen05 is unavailable: harness compiles for baseline compute_103, and all
//  tcgen05.* are sm_103a-family instructions. mma.sync bf16 is baseline PTX.)
//
// R17 fix: STAGE_B weight-row offset was an ELEMENT offset multiplied by DIMM
// again (mode 1 read ~1.7e8 elements OOB -> illegal memory access). wb is now
// a row offset. Also force 16B alignment on bf16 globals for cp.async.16.
//
// Inputs (metadata order):
//  0 x(8192,49,384) f32   1 mask(64,49,49) f32   2 rel_pos_table(169,12) f32
//  3 qkv_w(1152,384) f32  4 qkv_b(1152) f32      5 proj_w(384,384) f32
//  6 proj_b(384) f32      7 rel_pos_index(49,49) i32
// out (8192,49,384) f32

#define NTOK  49
#define NH    12
#define HDM   32
#define DIMM  384
#define NWIN  64
#define QKVN  1152
#define SCALE 0.17677669529663687f
#define MTOT  401408            // 8192*49, divisible by 128
#define MBLK  3136              // MTOT/128

// ---------------- scratch (__device__ globals; no runtime allocation) -------
__device__ float g_qkv[(size_t)MTOT * QKVN];              // qkv activations
__device__ float g_ao [(size_t)MTOT * DIMM];              // attention output
__device__ __align__(16) __nv_bfloat16 g_whi[(QKVN + DIMM) * DIMM];  // weight hi
__device__ __align__(16) __nv_bfloat16 g_wlo[(QKVN + DIMM) * DIMM];  // weight lo

// ---------------- PTX helpers ----------------------------------------------
__device__ __forceinline__ void cp16(uint32_t s, const void* g) {
    asm volatile("cp.async.cg.shared.global [%0], [%1], 16;" :: "r"(s), "l"(g));
}
__device__ __forceinline__ void cp_commit() {
    asm volatile("cp.async.commit_group;" ::: "memory");
}
__device__ __forceinline__ void cp_wait0() {
    asm volatile("cp.async.wait_group 0;" ::: "memory");
}
__device__ __forceinline__ void ldsm4(uint32_t* r, uint32_t a) {
    asm volatile("ldmatrix.sync.aligned.m8n8.x4.shared.b16 {%0,%1,%2,%3}, [%4];"
                 : "=r"(r[0]), "=r"(r[1]), "=r"(r[2]), "=r"(r[3]) : "r"(a));
}
__device__ __forceinline__ void mma16816(float* c, const uint32_t* a,
                                         const uint32_t* b) {
    asm volatile(
        "mma.sync.aligned.m16n8k16.row.col.f32.bf16.bf16.f32 "
        "{%0,%1,%2,%3}, {%4,%5,%6,%7}, {%8,%9}, {%0,%1,%2,%3};"
        : "+f"(c[0]), "+f"(c[1]), "+f"(c[2]), "+f"(c[3])
        : "r"(a[0]), "r"(a[1]), "r"(a[2]), "r"(a[3]), "r"(b[0]), "r"(b[1]));
}

#define SWZ(o) ((o) ^ (((o) >> 3) & 0x70))

// pack two floats to bf16x2 (and residuals)
__device__ __forceinline__ uint32_t pk_hi(float a, float b, float& ra, float& rb) {
    __nv_bfloat16 ha = __float2bfloat16(a), hb = __float2bfloat16(b);
    ra = a - __bfloat162float(ha);
    rb = b - __bfloat162float(hb);
    __nv_bfloat162 p; p.x = ha; p.y = hb;
    return *reinterpret_cast<uint32_t*>(&p);
}
__device__ __forceinline__ uint32_t pk(float a, float b) {
    __nv_bfloat162 p; p.x = __float2bfloat16(a); p.y = __float2bfloat16(b);
    return *reinterpret_cast<uint32_t*>(&p);
}

// ---------------- kernel 0: weight conversion -------------------------------
__global__ void wconv_kernel(const float* __restrict__ qkv_w,
                             const float* __restrict__ proj_w)
{
    const int tot = (QKVN + DIMM) * DIMM;
    for (int i = blockIdx.x * 256 + threadIdx.x; i < tot; i += gridDim.x * 256) {
        float w = (i < QKVN * DIMM) ? qkv_w[i] : proj_w[i - QKVN * DIMM];
        __nv_bfloat16 h = __float2bfloat16(w);
        g_whi[i] = h;
        g_wlo[i] = __float2bfloat16(w - __bfloat162float(h));
    }
}

// ---------------- kernels 1/3: split-bf16 HMMA GEMM -------------------------
// C[M x Ntot] = A[M x 384] @ W[Ntot x 384]^T + bias.
// CTA tile 128 x 192, K in 64-wide double-buffered smem chunks (SW128 swizzle).
// 8 warps as 4(M) x 2(N); warp tile 32 x 96 via mma.m16n8k16 bf16.
// 3 split terms per k16: Ah*Bh + Al*Bh + Ah*Bl.
// mode 0: A=x,    C=g_qkv (ldc 1152), W=qkv rows, SCALE on cols<384
// mode 1: A=g_ao, C=out   (ldc 384),  W=proj rows

#define A_OFF(b)   ((b) * 32768u)             // hi 16KB + lo 16KB per buffer
#define A_LO        16384u
#define B_OFF(b)   (65536u + (b) * 49152u)    // hi 24KB + lo 24KB per buffer
#define B_LO        24576u
#define GEMM_SMEM   163840

__global__ __launch_bounds__(256, 1)
void gemm_kernel(const float* __restrict__ Ap,
                 const float* __restrict__ bias,
                 float* __restrict__ Cout,
                 int mode)
{
    extern __shared__ char smem[];
    const uint32_t sb = (uint32_t)__cvta_generic_to_shared(smem);
    const int tid  = threadIdx.x;
    const int lane = tid & 31;
    const int warp = tid >> 5;
    const int m0   = blockIdx.x * 128;
    const int n0   = blockIdx.y * 192;

    const float* A  = mode ? g_ao : Ap;
    float*       C  = mode ? Cout : g_qkv;
    const int   ldc = mode ? DIMM : QKVN;
    const int    wb = mode ? QKVN : 0;        // weight ROW offset into g_whi/g_wlo
    const float  sc = (!mode && n0 < 384) ? SCALE : 1.0f;

    const float* Arow = A + (size_t)m0 * DIMM;

    // ---- per-lane swizzled fragment base offsets (chunk/step-invariant) ----
    const int wm = warp & 3;          // M sub-tile (32 rows)
    const int wn = warp >> 2;         // N sub-tile (96 cols)
    uint32_t swzA[2], swzB[6];
    {
        uint32_t kh = ((lane >> 4) & 1) * 16;      // A: lanes 16-31 -> k+8
        uint32_t row = (uint32_t)(wm * 32 + (lane & 15));
#pragma unroll
        for (int mi = 0; mi < 2; mi++) {
            uint32_t o = (row + 16u * mi) * 128u;
            swzA[mi] = (o ^ ((o >> 3) & 0x70)) ^ kh;
        }
        uint32_t bkh = ((lane >> 3) & 1) * 16;     // B: lanes 8-15/24-31 -> k+8
        uint32_t brow = (uint32_t)(wn * 96 + (lane & 7) + ((lane >> 4) & 1) * 8);
#pragma unroll
        for (int ni2 = 0; ni2 < 6; ni2++) {
            uint32_t o = (brow + 16u * ni2) * 128u;
            swzB[ni2] = (o ^ ((o >> 3) & 0x70)) ^ bkh;
        }
    }

    float acc[2][12][4];
#pragma unroll
    for (int mi = 0; mi < 2; mi++)
#pragma unroll
        for (int nj = 0; nj < 12; nj++)
#pragma unroll
            for (int e = 0; e < 4; e++) acc[mi][nj][e] = 0.f;

    // ---- staging macros ----
    // A chunk: 128 rows x 64 fp32 -> bf16 hi/lo, SW128-swizzled
#define STAGE_A(kk, bb) do {                                                   \
        const float* As = Arow + (kk);                                         \
        _Pragma("unroll")                                                      \
        for (int q = 0; q < 8; q++) {                                          \
            int idx = tid + 256 * q;                                           \
            int r = idx >> 4, k4 = idx & 15;                                   \
            float4 a = *(const float4*)(As + (size_t)r * DIMM + k4 * 4);       \
            float r0, r1, r2, r3;                                              \
            uint32_t h01 = pk_hi(a.x, a.y, r0, r1);                            \
            uint32_t h23 = pk_hi(a.z, a.w, r2, r3);                            \
            uint32_t off = SWZ((uint32_t)(r * 128 + k4 * 8));                  \
            *(uint2*)(smem + A_OFF(bb) + off)        = make_uint2(h01, h23);   \
            *(uint2*)(smem + A_OFF(bb) + A_LO + off) = make_uint2(pk(r0, r1),  \
                                                                  pk(r2, r3));\
        }                                                                      \
    } while (0)
    // B chunk: 192 rows x 64 bf16 (pre-converted) via cp.async, swizzled
#define STAGE_B(kk, bb) do {                                                   \
        _Pragma("unroll")                                                      \
        for (int q = 0; q < 6; q++) {                                          \
            int idx = tid + 256 * q;                                           \
            int r = idx >> 3, g = idx & 7;                                     \
            uint32_t off = SWZ((uint32_t)(r * 128 + g * 16));                  \
            size_t src = (size_t)(wb + n0 + r) * DIMM + (kk) + g * 8;          \
            cp16(sb + B_OFF(bb) + off,        g_whi + src);                    \
            cp16(sb + B_OFF(bb) + B_LO + off, g_wlo + src);                    \
        }                                                                      \
    } while (0)

    STAGE_A(0, 0);
    STAGE_B(0, 0);
    cp_commit();

#pragma unroll 1
    for (int c = 0; c < 6; c++) {
        const int bbuf = c & 1;
        cp_wait0();
        __syncthreads();                  // chunk c staged; prior buffer reads done
        if (c + 1 < 6) {                  // prefetch next chunk (other buffer)
            STAGE_A((c + 1) * 64, (c + 1) & 1);
            STAGE_B((c + 1) * 64, (c + 1) & 1);
            cp_commit();
        }

        const uint32_t aB = sb + A_OFF(bbuf);
        const uint32_t bB = sb + B_OFF(bbuf);
#pragma unroll
        for (int s = 0; s < 4; s++) {     // 4 k16 steps per 64-chunk
            const uint32_t sx = (uint32_t)(s * 32);
            uint32_t aH[2][4], aL[2][4], bF[6][4];
#pragma unroll
            for (int mi = 0; mi < 2; mi++) {
                ldsm4(aH[mi], aB + (swzA[mi] ^ sx));
                ldsm4(aL[mi], aB + A_LO + (swzA[mi] ^ sx));
            }
            // B hi: terms hh + lh
#pragma unroll
            for (int ni2 = 0; ni2 < 6; ni2++)
                ldsm4(bF[ni2], bB + (swzB[ni2] ^ sx));
#pragma unroll
            for (int mi = 0; mi < 2; mi++)
#pragma unroll
                for (int ni2 = 0; ni2 < 6; ni2++) {
                    mma16816(acc[mi][2 * ni2],     aH[mi], &bF[ni2][0]);
                    mma16816(acc[mi][2 * ni2 + 1], aH[mi], &bF[ni2][2]);
                    mma16816(acc[mi][2 * ni2],     aL[mi], &bF[ni2][0]);
                    mma16816(acc[mi][2 * ni2 + 1], aL[mi], &bF[ni2][2]);
                }
            // B lo: term hl
#pragma unroll
            for (int ni2 = 0; ni2 < 6; ni2++)
                ldsm4(bF[ni2], bB + B_LO + (swzB[ni2] ^ sx));
#pragma unroll
            for (int mi = 0; mi < 2; mi++)
#pragma unroll
                for (int ni2 = 0; ni2 < 6; ni2++) {
                    mma16816(acc[mi][2 * ni2],     aH[mi], &bF[ni2][0]);
                    mma16816(acc[mi][2 * ni2 + 1], aH[mi], &bF[ni2][2]);
                }
        }
    }

    // ---- epilogue: bounce through smem for coalesced 128B stores ----
    __syncthreads();                      // all buffer reads complete
    float* bbf = (float*)smem;            // 128 x 196 floats = 100,352 B
    const int g = lane >> 2, t = lane & 3;
#pragma unroll
    for (int mi = 0; mi < 2; mi++) {
        const int r = wm * 32 + 16 * mi + g;
#pragma unroll
        for (int nj = 0; nj < 12; nj++) {
            const int cc = wn * 96 + 8 * nj + 2 * t;
            *(float2*)&bbf[r * 196 + cc] =
                make_float2(acc[mi][nj][0], acc[mi][nj][1]);
            *(float2*)&bbf[(r + 8) * 196 + cc] =
                make_float2(acc[mi][nj][2], acc[mi][nj][3]);
        }
    }
    __syncthreads();
#pragma unroll
    for (int q = 0; q < 24; q++) {
        int idx = tid + 256 * q;          // 0..6143 : 128 rows x 48 float4
        int r = idx / 48, c4 = idx % 48;
        const float* p = &bbf[r * 196 + c4 * 4];
        float4 v;
        v.x = (p[0] + bias[n0 + c4 * 4 + 0]) * sc;
        v.y = (p[1] + bias[n0 + c4 * 4 + 1]) * sc;
        v.z = (p[2] + bias[n0 + c4 * 4 + 2]) * sc;
        v.w = (p[3] + bias[n0 + c4 * 4 + 3]) * sc;
        *(float4*)(C + (size_t)(m0 + r) * ldc + n0 + c4 * 4) = v;
    }
#undef STAGE_A
#undef STAGE_B
}

// ---------------- kernel 2: fp32 attention per window -----------------------
__global__ __launch_bounds__(256) void attn_kernel(const float* __restrict__ mask,
                                                   const float* __restrict__ tbl,
                                                   const int*   __restrict__ rpi)
{
    __shared__ float QS[NTOK * 32];
    __shared__ float KS[NTOK * 36];
    __shared__ float VS[NTOK * 32];
    __shared__ float PS[NTOK * 52];

    const int tid  = threadIdx.x;
    const int lane = tid & 31;
    const int warp = tid >> 5;
    const int b    = blockIdx.x;
    const float* mw = mask + (size_t)(b & (NWIN - 1)) * NTOK * NTOK;

    const bool v2  = (lane + 32) < NTOK;
    const int  jc2 = v2 ? lane + 32 : 0;
    const size_t tok0 = (size_t)b * NTOK;

#pragma unroll 1
    for (int h = 0; h < NH; h++) {
        __syncthreads();                  // prior head's smem reads done
        for (int i = tid; i < NTOK * 32; i += 256) {
            int r = i >> 5, d = i & 31;
            size_t base = (tok0 + r) * QKVN + h * HDM + d;
            QS[r * 32 + d] = g_qkv[base];          // q (scaled+biased in GEMM)
            KS[r * 36 + d] = g_qkv[base + 384];    // k
            VS[r * 32 + d] = g_qkv[base + 768];    // v
        }
        __syncthreads();

        // scores + bias + mask + softmax (warp handles rows {warp + 8j})
#pragma unroll
        for (int j = 0; j < 7; j++) {
            if (j == 6 && warp != 0) break;
            int r = warp + 8 * j;
            int   i1 = rpi[r * NTOK + lane];
            float m1 = mw [r * NTOK + lane];
            int   i2 = v2 ? rpi[r * NTOK + lane + 32] : 0;
            float m2 = v2 ? mw [r * NTOK + lane + 32] : 0.f;
            float t1 = tbl[i1 * NH + h];
            float t2 = tbl[i2 * NH + h];
            float s1 = 0.f, s2 = 0.f;
#pragma unroll
            for (int dq = 0; dq < 8; dq++) {
                float4 q  = *(const float4*)&QS[r    * 32 + dq * 4];
                float4 k1 = *(const float4*)&KS[lane * 36 + dq * 4];
                float4 k2 = *(const float4*)&KS[jc2  * 36 + dq * 4];
                s1 = fmaf(q.x, k1.x, s1); s1 = fmaf(q.y, k1.y, s1);
                s1 = fmaf(q.z, k1.z, s1); s1 = fmaf(q.w, k1.w, s1);
                s2 = fmaf(q.x, k2.x, s2); s2 = fmaf(q.y, k2.y, s2);
                s2 = fmaf(q.z, k2.z, s2); s2 = fmaf(q.w, k2.w, s2);
            }
            s1 += t1 + m1;
            s2 = v2 ? (s2 + t2 + m2) : -1e30f;
            float mx = fmaxf(s1, s2);
#pragma unroll
            for (int o = 16; o > 0; o >>= 1)
                mx = fmaxf(mx, __shfl_xor_sync(0xffffffffu, mx, o));
            float e1 = __expf(s1 - mx);
            float e2 = v2 ? __expf(s2 - mx) : 0.f;
            float sum = e1 + e2;
#pragma unroll
            for (int o = 16; o > 0; o >>= 1)
                sum += __shfl_xor_sync(0xffffffffu, sum, o);
            float inv = 1.0f / sum;
            PS[r * 52 + lane] = e1 * inv;
            if (v2) PS[r * 52 + lane + 32] = e2 * inv;
        }
        __syncwarp();

        // P @ V -> attn-out scratch
        float o[7];
#pragma unroll
        for (int j = 0; j < 7; j++) o[j] = 0.f;
#pragma unroll 3
        for (int jq = 0; jq < 12; jq++) {
            float va = VS[(4 * jq + 0) * 32 + lane];
            float vb = VS[(4 * jq + 1) * 32 + lane];
            float vc = VS[(4 * jq + 2) * 32 + lane];
            float vd = VS[(4 * jq + 3) * 32 + lane];
#pragma unroll
            for (int j = 0; j < 7; j++) {
                if (j < 6 || warp == 0) {
                    float4 pp = *(const float4*)&PS[(warp + 8 * j) * 52 + 4 * jq];
                    o[j] = fmaf(pp.x, va, o[j]);
                    o[j] = fmaf(pp.y, vb, o[j]);
                    o[j] = fmaf(pp.z, vc, o[j]);
                    o[j] = fmaf(pp.w, vd, o[j]);
                }
            }
        }
        float vt = VS[48 * 32 + lane];
#pragma unroll
        for (int j = 0; j < 7; j++) {
            if (j < 6 || warp == 0) {
                int r = warp + 8 * j;
                o[j] = fmaf(PS[r * 52 + 48], vt, o[j]);
                g_ao[(tok0 + r) * DIMM + h * HDM + lane] = o[j];
            }
        }
        __syncwarp();
    }
}

// ---------------- launch ----------------------------------------------------
extern "C" void kernel_launch(void* const* d_in, const int* in_sizes, int n_in,
                              void* d_out, int out_size)
{
    const float* x      = (const float*)d_in[0];
    const float* mask   = (const float*)d_in[1];
    const float* tbl    = (const float*)d_in[2];
    const float* qkv_w  = (const float*)d_in[3];
    const float* qkv_b  = (const float*)d_in[4];
    const float* proj_w = (const float*)d_in[5];
    const float* proj_b = (const float*)d_in[6];
    const int*   rpi    = (const int*)d_in[7];
    float* out = (float*)d_out;

    cudaFuncSetAttribute(gemm_kernel,
                         cudaFuncAttributeMaxDynamicSharedMemorySize, GEMM_SMEM);

    // 0) weights -> bf16 hi/lo
    wconv_kernel<<<288, 256>>>(qkv_w, proj_w);
    // 1) QKV GEMM: (401408 x 384) @ (1152 x 384)^T -> g_qkv (q pre-scaled)
    gemm_kernel<<<dim3(MBLK, 6), 256, GEMM_SMEM>>>(x, qkv_b, out, 0);
    // 2) attention -> g_ao
    attn_kernel<<<MTOT / NTOK, 256>>>(mask, tbl, rpi);
    // 3) proj GEMM: (401408 x 384) @ (384 x 384)^T -> out
    gemm_kernel<<<dim3(MBLK, 2), 256, GEMM_SMEM>>>(x, proj_b, out, 1);
}